// round 13
// baseline (speedup 1.0000x reference)
#include <cuda_runtime.h>
#include <cuda_bf16.h>
#include <math.h>

// Problem constants: N=32768, M=8192, D=384, K=9
#define NN 32768
#define MM 8192
#define DD 384
#define KK 9

#define BM 64                  // embedding rows per CTA
#define BN 128                 // bank cols per tile
#define BK 64                  // k per chunk
#define NKC (DD / BK)          // 6
#define NMIT (MM / BN)         // 64
#define NCHUNKS (NMIT * NKC)   // 384
#define NB 3                   // B buffers

#define A_STRIDE_BF 392        // 384+8 pad; conflict-free ldmatrix
#define A_ROW_BYTES (A_STRIDE_BF * 2)       // 784
#define A_BYTES (BM * A_ROW_BYTES)          // 50176
#define B_STRIDE_BF 72         // 64+8 pad
#define B_ROW_BYTES (B_STRIDE_BF * 2)       // 144
#define B_BUF_BYTES (BN * B_ROW_BYTES)      // 18432
#define CAND_STRIDE 145        // 16 lists * 9 + 1

#define OFF_B    A_BYTES                         // 50176
#define OFF_YN   (OFF_B + NB * B_BUF_BYTES)      // 105472
#define OFF_MBAR (OFF_YN + 2 * BN * 4)           // 106496
#define SMEM_BYTES (OFF_MBAR + 64)               // 106560 (2 CTAs/SM)
// cand (64*145*4 = 37120 B) overlays the B buffers after the main loop

__device__ __align__(16) __nv_bfloat16 g_Abf[(size_t)NN * DD];
__device__ __align__(16) __nv_bfloat16 g_Bbf[(size_t)MM * DD];
__device__ __align__(16) float g_xnorm[NN];
__device__ __align__(16) float g_ynorm[MM];

// ---------------- helpers ----------------
__device__ __forceinline__ unsigned smem_u32(const void* p) {
    unsigned a;
    asm("{ .reg .u64 t; cvta.to.shared.u64 t, %1; cvt.u32.u64 %0, t; }" : "=r"(a) : "l"(p));
    return a;
}
#define CP_ASYNC16(dst, src) asm volatile("cp.async.cg.shared.global [%0], [%1], 16;" :: "r"(dst), "l"(src) : "memory")
#define CP_COMMIT()  asm volatile("cp.async.commit_group;" ::: "memory")
#define CP_WAIT0()   asm volatile("cp.async.wait_group 0;" ::: "memory")
#define CP_MBAR_ARRIVE(mb) asm volatile("cp.async.mbarrier.arrive.noinc.shared.b64 [%0];" :: "r"(mb) : "memory")

#define MBINIT(a, c) asm volatile("mbarrier.init.shared.b64 [%0], %1;" :: "r"(a), "r"(c) : "memory")
#define MBARRIVE(a)  asm volatile("mbarrier.arrive.shared.b64 _, [%0];" :: "r"(a) : "memory")
#define MBWAIT(addr, parity) do {                                              \
    unsigned _m = (addr), _p = (parity), _d;                                   \
    asm volatile("{\n\t.reg .pred p;\n\t"                                      \
        "mbarrier.try_wait.parity.acquire.cta.shared::cta.b64 p, [%1], %2;\n\t"\
        "selp.b32 %0, 1, 0, p;\n\t}" : "=r"(_d) : "r"(_m), "r"(_p) : "memory");\
    if (!_d) {                                                                 \
        asm volatile("{\n\t.reg .pred P1;\n\t"                                 \
            "WL_%=:\n\t"                                                       \
            "mbarrier.try_wait.parity.acquire.cta.shared::cta.b64 P1, [%0], %1, 0x989680;\n\t" \
            "@P1 bra.uni WD_%=;\n\t"                                           \
            "bra.uni WL_%=;\n\t"                                               \
            "WD_%=:\n\t}" :: "r"(_m), "r"(_p) : "memory");                     \
    }                                                                          \
} while (0)

#define LDSM4(r, addr) \
    asm volatile("ldmatrix.sync.aligned.m8n8.x4.shared.b16 {%0,%1,%2,%3}, [%4];" \
        : "=r"((r)[0]), "=r"((r)[1]), "=r"((r)[2]), "=r"((r)[3]) : "r"(addr))

#define MMA_16816(d, a, b0, b1) \
    asm volatile("mma.sync.aligned.m16n8k16.row.col.f32.bf16.bf16.f32 " \
        "{%0,%1,%2,%3}, {%4,%5,%6,%7}, {%8,%9}, {%0,%1,%2,%3};" \
        : "+f"((d)[0]), "+f"((d)[1]), "+f"((d)[2]), "+f"((d)[3]) \
        : "r"((a)[0]), "r"((a)[1]), "r"((a)[2]), "r"((a)[3]), "r"(b0), "r"(b1))

// ---------------- merged convert + norm pre-pass ----------------
__global__ void conv_all(const float* __restrict__ x, const float* __restrict__ y) {
    int bid = blockIdx.x;
    const float* src;
    __nv_bfloat16* dst;
    float* norm;
    int row;
    if (bid < NN / 8) {
        row = bid * 8 + threadIdx.y;
        src = x; dst = g_Abf; norm = g_xnorm;
    } else {
        row = (bid - NN / 8) * 8 + threadIdx.y;
        src = y; dst = g_Bbf; norm = g_ynorm;
    }
    const float4* s4 = (const float4*)(src + (size_t)row * DD);
    __nv_bfloat162* d2p = (__nv_bfloat162*)(dst + (size_t)row * DD);
    float s = 0.f;
    for (int c = threadIdx.x; c < DD / 4; c += 32) {
        float4 v = s4[c];
        s += v.x * v.x + v.y * v.y + v.z * v.z + v.w * v.w;
        d2p[c * 2 + 0] = __floats2bfloat162_rn(v.x, v.y);
        d2p[c * 2 + 1] = __floats2bfloat162_rn(v.z, v.w);
    }
#pragma unroll
    for (int o = 16; o > 0; o >>= 1) s += __shfl_xor_sync(0xFFFFFFFFu, s, o);
    if (threadIdx.x == 0) norm[row] = s;
}

// Rare path: branchless sorted shift, executed only when v < t[KK-1].
__device__ __forceinline__ void top9_shift(float* t, float v) {
#pragma unroll
    for (int p = KK - 1; p > 0; --p)
        t[p] = (v < t[p - 1]) ? t[p - 1] : fminf(v, t[p]);
    t[0] = fminf(t[0], v);
}

// ---------------- main fused kernel ----------------
// 288 threads: 8 consumer warps (2Mx4N grid, 32x32 tiles) + 1 producer warp.
// Producer streams B + yn via cp.async, arms full[] via cp.async.mbarrier.arrive.
// Consumers free-run on mbarriers; no __syncthreads in the main loop.
__global__ void __launch_bounds__(288, 2) fapm_mma(float* __restrict__ out) {
    extern __shared__ char smem[];
    float* ynS  = (float*)(smem + OFF_YN);
    float* cand = (float*)(smem + OFF_B);   // overlay, used after main loop

    const int tid = threadIdx.x;
    const int l = tid & 31;
    const int row0 = blockIdx.x * BM;

    const unsigned Abase = smem_u32(smem);
    const unsigned Bbase = Abase + OFF_B;
    const unsigned ynB   = Abase + OFF_YN;
    const unsigned fullB  = Abase + OFF_MBAR;        // 3 x 8B
    const unsigned emptyB = Abase + OFF_MBAR + 24;   // 3 x 8B

    if (tid == 0) {
#pragma unroll
        for (int b = 0; b < NB; ++b) {
            MBINIT(fullB + 8 * b, 32);     // producer lanes (hw arrive)
            MBINIT(emptyB + 8 * b, 256);   // consumer threads
        }
    }
    __syncthreads();

    if (tid >= 256) {
        // ================= producer warp =================
        const int k8 = l & 7, n0 = l >> 3;            // n0: 0..3
        const __nv_bfloat16* src = g_Bbf + (size_t)n0 * DD + k8 * 8;
        const unsigned dlane = n0 * B_ROW_BYTES + k8 * 16;
        int c = 0, mi = 0, b = 0, ph = 1;
#pragma unroll 1
        for (int cc = 0; cc < NCHUNKS; ++cc) {
            MBWAIT(emptyB + 8 * b, (unsigned)ph);
            unsigned dstb = Bbase + b * B_BUF_BYTES + dlane;
            const __nv_bfloat16* s = src;
#pragma unroll
            for (int i = 0; i < 32; ++i) {
                CP_ASYNC16(dstb + i * 4 * B_ROW_BYTES, (const void*)s);
                s += 4 * DD;
            }
            if (c == 0)  // yn for this tile rides with chunk 0's group
                CP_ASYNC16(ynB + (mi & 1) * (BN * 4) + l * 16,
                           (const void*)(g_ynorm + mi * BN + l * 4));
            CP_COMMIT();
            CP_MBAR_ARRIVE(fullB + 8 * b);
            src += BK;
            if (++c == NKC) { c = 0; ++mi; src += (size_t)BN * DD - DD; }
            if (++b == NB) { b = 0; ph ^= 1; }
        }
    } else {
        // ================= consumer warps =================
        const int w = tid >> 5;
        const int wm = w >> 2;     // 0..1 : M position (32 rows each)
        const int wn = w & 3;      // 0..3 : N position (32 cols each)

        // stage A (64 x 384 bf16) cooperatively (256 threads)
        {
            const __nv_bfloat16* Ag = g_Abf + (size_t)row0 * DD;
#pragma unroll
            for (int i = 0; i < 12; ++i) {
                int idx = tid + i * 256;        // 3072 slots of 16B
                int r = idx / 48, sl = idx % 48;
                CP_ASYNC16(Abase + r * A_ROW_BYTES + sl * 16,
                           (const void*)(Ag + (size_t)r * DD + sl * 8));
            }
            CP_COMMIT();
            CP_WAIT0();
            asm volatile("bar.sync 1, 256;" ::: "memory");
        }

        float xn[4];
#pragma unroll
        for (int g = 0; g < 4; ++g) xn[g] = g_xnorm[row0 + wm * 32 + (l >> 2) + g * 8];

        const unsigned a_off = Abase + (wm * 32 + (l & 15)) * A_ROW_BYTES + ((l & 16) ? 16 : 0);
        const unsigned b_lane = ((l & 7) + ((l & 16) ? 8 : 0)) * B_ROW_BYTES + ((l & 8) ? 16 : 0)
                                + wn * 32 * B_ROW_BYTES;

        float tk[4][KK];
        float thr[4];
#pragma unroll
        for (int g = 0; g < 4; ++g) {
            thr[g] = 3.4e38f;
#pragma unroll
            for (int j = 0; j < KK; ++j) tk[g][j] = 3.4e38f;
        }

        float acc[32];
#pragma unroll
        for (int i = 0; i < 32; ++i) acc[i] = 0.f;

        int c6 = 0, mi = 0, b = 0, ph = 0;
#pragma unroll 1
        for (int cc = 0; cc < NCHUNKS; ++cc) {
            MBWAIT(fullB + 8 * b, (unsigned)ph);

            // compute chunk from buffer b: 4 k-steps of k16
            {
                const unsigned bbuf = Bbase + b * B_BUF_BYTES + b_lane;
                const unsigned abuf = a_off + c6 * 128;
#pragma unroll
                for (int ks = 0; ks < 4; ++ks) {
                    unsigned a0[4], a1[4];
                    LDSM4(a0, abuf + ks * 32);
                    LDSM4(a1, abuf + 16 * A_ROW_BYTES + ks * 32);
#pragma unroll
                    for (int i = 0; i < 2; ++i) {
                        unsigned bf[4];
                        LDSM4(bf, bbuf + i * 16 * B_ROW_BYTES + ks * 32);
                        MMA_16816(acc + (i * 2 + 0) * 4,      a0, bf[0], bf[1]);
                        MMA_16816(acc + (i * 2 + 1) * 4,      a0, bf[2], bf[3]);
                        MMA_16816(acc + 16 + (i * 2 + 0) * 4, a1, bf[0], bf[1]);
                        MMA_16816(acc + 16 + (i * 2 + 1) * 4, a1, bf[2], bf[3]);
                    }
                }
            }
            MBARRIVE(emptyB + 8 * b);

            // epilogue at end of tile: cheap threshold check, rare branchy insert
            if (c6 == 5) {
                const float* yn = &ynS[(mi & 1) * BN + wn * 32 + (l & 3) * 2];
#pragma unroll
                for (int mg = 0; mg < 2; ++mg) {
#pragma unroll
                    for (int nt = 0; nt < 4; ++nt) {
                        float yn0 = yn[nt * 8];
                        float yn1 = yn[nt * 8 + 1];
                        float* ac = acc + mg * 16 + nt * 4;
                        float v;
                        v = fmaf(-2.f, ac[0], xn[mg * 2 + 0] + yn0);
                        if (v < thr[mg * 2 + 0]) { top9_shift(tk[mg * 2 + 0], v); thr[mg * 2 + 0] = tk[mg * 2 + 0][KK - 1]; }
                        v = fmaf(-2.f, ac[1], xn[mg * 2 + 0] + yn1);
                        if (v < thr[mg * 2 + 0]) { top9_shift(tk[mg * 2 + 0], v); thr[mg * 2 + 0] = tk[mg * 2 + 0][KK - 1]; }
                        v = fmaf(-2.f, ac[2], xn[mg * 2 + 1] + yn0);
                        if (v < thr[mg * 2 + 1]) { top9_shift(tk[mg * 2 + 1], v); thr[mg * 2 + 1] = tk[mg * 2 + 1][KK - 1]; }
                        v = fmaf(-2.f, ac[3], xn[mg * 2 + 1] + yn1);
                        if (v < thr[mg * 2 + 1]) { top9_shift(tk[mg * 2 + 1], v); thr[mg * 2 + 1] = tk[mg * 2 + 1][KK - 1]; }
                    }
                }
#pragma unroll
                for (int i = 0; i < 32; ++i) acc[i] = 0.f;
            }

            if (++c6 == NKC) { c6 = 0; ++mi; }
            if (++b == NB) { b = 0; ph ^= 1; }
        }

        // stash per-thread lists (cand overlays B buffers after full-CTA sync below)
        __syncthreads();
        const int lst = wn * 4 + (l & 3);   // 0..15
#pragma unroll
        for (int g = 0; g < 4; ++g) {
            int r = wm * 32 + (l >> 2) + g * 8;
#pragma unroll
            for (int j = 0; j < KK; ++j)
                cand[r * CAND_STRIDE + lst * KK + j] = tk[g][j];
        }
    }

    if (tid >= 256) __syncthreads();   // producer joins the pre-overlay sync
    __syncthreads();                   // all 288: lists written

    if (tid < BM) {
        float* c = &cand[tid * CAND_STRIDE];
        float* o = out + (size_t)(row0 + tid) * KK;
        const int NC = 16 * KK;   // 144
#pragma unroll 1
        for (int k = 0; k < KK; ++k) {
            float mv = c[k];
            int mi2 = k;
            for (int j = k + 1; j < NC; ++j) {
                float v = c[j];
                if (v < mv) { mv = v; mi2 = j; }
            }
            c[mi2] = c[k];
            c[k] = mv;
            o[k] = sqrtf(fmaxf(mv, 0.f));
        }
    }
}

extern "C" void kernel_launch(void* const* d_in, const int* in_sizes, int n_in,
                              void* d_out, int out_size) {
    const float* emb = (const float*)d_in[0];   // [N, D] fp32
    const float* mem = (const float*)d_in[1];   // [M, D] fp32
    float* out = (float*)d_out;                 // [N, K] fp32

    dim3 cb(32, 8);
    conv_all<<<NN / 8 + MM / 8, cb>>>(emb, mem);

    cudaFuncSetAttribute(fapm_mma, cudaFuncAttributeMaxDynamicSharedMemorySize, SMEM_BYTES);
    fapm_mma<<<NN / BM, 288, SMEM_BYTES>>>(out);
}

// round 14
// speedup vs baseline: 1.0125x; 1.0125x over previous
#include <cuda_runtime.h>
#include <cuda_bf16.h>
#include <math.h>

// Problem constants: N=32768, M=8192, D=384, K=9
#define NN 32768
#define MM 8192
#define DD 384
#define KK 9

#define BM 64                  // embedding rows per CTA
#define BN 128                 // bank cols per tile
#define BK 64                  // k per chunk
#define NKC (DD / BK)          // 6
#define NMIT (MM / BN)         // 64
#define NCHUNKS (NMIT * NKC)   // 384
#define NB 3                   // B buffers

#define A_STRIDE_BF 392        // 384+8 pad; conflict-free ldmatrix
#define A_ROW_BYTES (A_STRIDE_BF * 2)       // 784
#define A_BYTES (BM * A_ROW_BYTES)          // 50176
#define B_STRIDE_BF 72         // 64+8 pad
#define B_ROW_BYTES (B_STRIDE_BF * 2)       // 144
#define B_BUF_BYTES (BN * B_ROW_BYTES)      // 18432
#define CAND_STRIDE 145        // 16 lists * 9 + 1

#define OFF_B   A_BYTES                          // 50176
#define OFF_YN  (OFF_B + NB * B_BUF_BYTES)       // 105472
#define SMEM_BYTES (OFF_YN + 2 * BN * 4)         // 106496  (2 CTAs/SM)
// cand (64*145*4 = 37120 B) overlays the B buffers after the main loop

__device__ __align__(16) __nv_bfloat16 g_Abf[(size_t)NN * DD];
__device__ __align__(16) __nv_bfloat16 g_Bbf[(size_t)MM * DD];
__device__ __align__(16) float g_xnorm[NN];
__device__ __align__(16) float g_ynorm[MM];

// ---------------- helpers ----------------
__device__ __forceinline__ unsigned smem_u32(const void* p) {
    unsigned a;
    asm("{ .reg .u64 t; cvta.to.shared.u64 t, %1; cvt.u32.u64 %0, t; }" : "=r"(a) : "l"(p));
    return a;
}
#define CP_ASYNC16(dst, src) asm volatile("cp.async.cg.shared.global [%0], [%1], 16;" :: "r"(dst), "l"(src) : "memory")
// reg+imm addressing on both sides: one base pointer, compile-time offsets
#define CP_ASYNC16_OFF(dst, doff, src, soff) \
    asm volatile("cp.async.cg.shared.global [%0+%2], [%1+%3], 16;" \
        :: "r"(dst), "l"(src), "n"(doff), "n"(soff) : "memory")
#define CP_COMMIT()  asm volatile("cp.async.commit_group;" ::: "memory")
#define CP_WAIT0()   asm volatile("cp.async.wait_group 0;" ::: "memory")
#define CP_WAIT1()   asm volatile("cp.async.wait_group 1;" ::: "memory")

#define LDSM4(r, addr) \
    asm volatile("ldmatrix.sync.aligned.m8n8.x4.shared.b16 {%0,%1,%2,%3}, [%4];" \
        : "=r"((r)[0]), "=r"((r)[1]), "=r"((r)[2]), "=r"((r)[3]) : "r"(addr))

#define MMA_16816(d, a, b0, b1) \
    asm volatile("mma.sync.aligned.m16n8k16.row.col.f32.bf16.bf16.f32 " \
        "{%0,%1,%2,%3}, {%4,%5,%6,%7}, {%8,%9}, {%0,%1,%2,%3};" \
        : "+f"((d)[0]), "+f"((d)[1]), "+f"((d)[2]), "+f"((d)[3]) \
        : "r"((a)[0]), "r"((a)[1]), "r"((a)[2]), "r"((a)[3]), "r"(b0), "r"(b1))

// ---------------- merged convert + norm pre-pass ----------------
__global__ void conv_all(const float* __restrict__ x, const float* __restrict__ y) {
    int bid = blockIdx.x;
    const float* src;
    __nv_bfloat16* dst;
    float* norm;
    int row;
    if (bid < NN / 8) {
        row = bid * 8 + threadIdx.y;
        src = x; dst = g_Abf; norm = g_xnorm;
    } else {
        row = (bid - NN / 8) * 8 + threadIdx.y;
        src = y; dst = g_Bbf; norm = g_ynorm;
    }
    const float4* s4 = (const float4*)(src + (size_t)row * DD);
    __nv_bfloat162* d2p = (__nv_bfloat162*)(dst + (size_t)row * DD);
    float s = 0.f;
    for (int c = threadIdx.x; c < DD / 4; c += 32) {
        float4 v = s4[c];
        s += v.x * v.x + v.y * v.y + v.z * v.z + v.w * v.w;
        d2p[c * 2 + 0] = __floats2bfloat162_rn(v.x, v.y);
        d2p[c * 2 + 1] = __floats2bfloat162_rn(v.z, v.w);
    }
#pragma unroll
    for (int o = 16; o > 0; o >>= 1) s += __shfl_xor_sync(0xFFFFFFFFu, s, o);
    if (threadIdx.x == 0) norm[row] = s;
}

// Rare path: branchless sorted shift, executed only when v < t[KK-1].
__device__ __forceinline__ void top9_shift(float* t, float v) {
#pragma unroll
    for (int p = KK - 1; p > 0; --p)
        t[p] = (v < t[p - 1]) ? t[p - 1] : fminf(v, t[p]);
    t[0] = fminf(t[0], v);
}

// ---------------- main fused kernel ----------------
// 256 threads = 8 warps = 2 (M) x 4 (N). Warp tile: 32 rows x 32 cols.
// 2 CTAs/SM. Per k-step: all 4 fragment LDSMs issued up front, then 16 MMAs
// (decouples LDSM latency from MMA issue). Single-pointer B streaming.
__global__ void __launch_bounds__(256, 2) fapm_mma(float* __restrict__ out) {
    extern __shared__ char smem[];
    float* ynS  = (float*)(smem + OFF_YN);
    float* cand = (float*)(smem + OFF_B);   // overlay, used after main loop

    const int tid = threadIdx.x;
    const int l = tid & 31;
    const int w = tid >> 5;
    const int wm = w >> 2;     // 0..1 : M position (32 rows each)
    const int wn = w & 3;      // 0..3 : N position (32 cols each)
    const int row0 = blockIdx.x * BM;

    const unsigned Abase = smem_u32(smem);
    const unsigned Bbase = Abase + OFF_B;

    // per-thread B-load lane mapping (4 x 16B per chunk, rows ld_n0 + {0,32,64,96})
    const int ld_n0 = tid >> 3;          // 0..31
    const int ld_k8 = tid & 7;

    // ---- group 0: stage A (64 x 384 bf16) ----
    {
        const __nv_bfloat16* Ag = g_Abf + (size_t)row0 * DD;
#pragma unroll
        for (int i = 0; i < 12; ++i) {
            int idx = tid + i * 256;        // 3072 slots of 16B
            int r = idx / 48, sl = idx % 48;
            CP_ASYNC16(Abase + r * A_ROW_BYTES + sl * 16,
                       (const void*)(Ag + (size_t)r * DD + sl * 8));
        }
        CP_COMMIT();
    }

    // single persistent B source pointer (row ld_n0, this thread's 16B lane)
    const __nv_bfloat16* bsrc0 = g_Bbf + (size_t)ld_n0 * DD + ld_k8 * 8;
    const unsigned bdst0 = Bbase + ld_n0 * B_ROW_BYTES + ld_k8 * 16;

    // ---- groups 1,2: B chunks 0,1 (tile 0) ----
#pragma unroll
    for (int ck = 0; ck < 2; ++ck) {
        const __nv_bfloat16* s = bsrc0 + ck * BK;
        const unsigned d = bdst0 + ck * B_BUF_BYTES;
        CP_ASYNC16_OFF(d, 0 * 32 * B_ROW_BYTES, s, 0 * 32 * DD * 2);
        CP_ASYNC16_OFF(d, 1 * 32 * B_ROW_BYTES, s, 1 * 32 * DD * 2);
        CP_ASYNC16_OFF(d, 2 * 32 * B_ROW_BYTES, s, 2 * 32 * DD * 2);
        CP_ASYNC16_OFF(d, 3 * 32 * B_ROW_BYTES, s, 3 * 32 * DD * 2);
        CP_COMMIT();
    }
    bsrc0 += 2 * BK;   // positioned at chunk (mi=0, c=2)

    // 4 global rows per thread: wm*32 + (l>>2) + {0,8,16,24}
    float xn[4];
#pragma unroll
    for (int g = 0; g < 4; ++g) xn[g] = g_xnorm[row0 + wm * 32 + (l >> 2) + g * 8];

    const unsigned a_off = Abase + (wm * 32 + (l & 15)) * A_ROW_BYTES + ((l & 16) ? 16 : 0);
    const unsigned b_lane = ((l & 7) + ((l & 16) ? 8 : 0)) * B_ROW_BYTES + ((l & 8) ? 16 : 0)
                            + wn * 32 * B_ROW_BYTES;

    float tk[4][KK];
    float thr[4];
#pragma unroll
    for (int g = 0; g < 4; ++g) {
        thr[g] = 3.4e38f;
#pragma unroll
        for (int j = 0; j < KK; ++j) tk[g][j] = 3.4e38f;
    }

    float acc[32];
#pragma unroll
    for (int i = 0; i < 32; ++i) acc[i] = 0.f;

    // chunk-stream counters
    int c6 = 0, mi = 0, b3 = 0;          // current chunk: phase-in-tile, tile, buffer
    int is_c = 2, is_b3 = 2;             // issue cursor (chunk cc+2)

#pragma unroll 1
    for (int cc = 0; cc < NCHUNKS; ++cc) {
        if (cc >= NCHUNKS - 2) { CP_WAIT0(); } else { CP_WAIT1(); }
        __syncthreads();

        if (c6 == 0 && tid < BN)
            ynS[(mi & 1) * BN + tid] = g_ynorm[mi * BN + tid];

        // issue chunk cc+2 (single pointer + immediate offsets)
        if (cc + 2 < NCHUNKS) {
            const unsigned d = bdst0 + is_b3 * B_BUF_BYTES;
            CP_ASYNC16_OFF(d, 0 * 32 * B_ROW_BYTES, bsrc0, 0 * 32 * DD * 2);
            CP_ASYNC16_OFF(d, 1 * 32 * B_ROW_BYTES, bsrc0, 1 * 32 * DD * 2);
            CP_ASYNC16_OFF(d, 2 * 32 * B_ROW_BYTES, bsrc0, 2 * 32 * DD * 2);
            CP_ASYNC16_OFF(d, 3 * 32 * B_ROW_BYTES, bsrc0, 3 * 32 * DD * 2);
            CP_COMMIT();
            bsrc0 += (is_c == NKC - 1) ? ((long)BN * DD - (NKC - 1) * BK) : (long)BK;
            if (++is_c == NKC) is_c = 0;
            if (++is_b3 == NB) is_b3 = 0;
        }

        // compute chunk cc: 4 k-steps; all 4 LDSMs issued before the 16 MMAs
        {
            const unsigned bbuf = Bbase + b3 * B_BUF_BYTES + b_lane;
            const unsigned abuf = a_off + c6 * 128;
#pragma unroll
            for (int ks = 0; ks < 4; ++ks) {
                unsigned a0[4], a1[4], bf[4], bf2[4];
                LDSM4(a0, abuf + ks * 32);
                LDSM4(a1, abuf + 16 * A_ROW_BYTES + ks * 32);
                LDSM4(bf,  bbuf + ks * 32);
                LDSM4(bf2, bbuf + 16 * B_ROW_BYTES + ks * 32);
                MMA_16816(acc + 0,  a0, bf[0],  bf[1]);
                MMA_16816(acc + 4,  a0, bf[2],  bf[3]);
                MMA_16816(acc + 16, a1, bf[0],  bf[1]);
                MMA_16816(acc + 20, a1, bf[2],  bf[3]);
                MMA_16816(acc + 8,  a0, bf2[0], bf2[1]);
                MMA_16816(acc + 12, a0, bf2[2], bf2[3]);
                MMA_16816(acc + 24, a1, bf2[0], bf2[1]);
                MMA_16816(acc + 28, a1, bf2[2], bf2[3]);
            }
        }

        // epilogue at end of tile: cheap threshold check, rare branchy insert
        if (c6 == 5) {
            const float* yn = &ynS[(mi & 1) * BN + wn * 32 + (l & 3) * 2];
#pragma unroll
            for (int mg = 0; mg < 2; ++mg) {
#pragma unroll
                for (int nt = 0; nt < 4; ++nt) {
                    float yn0 = yn[nt * 8];
                    float yn1 = yn[nt * 8 + 1];
                    float* ac = acc + mg * 16 + nt * 4;
                    float v;
                    v = fmaf(-2.f, ac[0], xn[mg * 2 + 0] + yn0);
                    if (v < thr[mg * 2 + 0]) { top9_shift(tk[mg * 2 + 0], v); thr[mg * 2 + 0] = tk[mg * 2 + 0][KK - 1]; }
                    v = fmaf(-2.f, ac[1], xn[mg * 2 + 0] + yn1);
                    if (v < thr[mg * 2 + 0]) { top9_shift(tk[mg * 2 + 0], v); thr[mg * 2 + 0] = tk[mg * 2 + 0][KK - 1]; }
                    v = fmaf(-2.f, ac[2], xn[mg * 2 + 1] + yn0);
                    if (v < thr[mg * 2 + 1]) { top9_shift(tk[mg * 2 + 1], v); thr[mg * 2 + 1] = tk[mg * 2 + 1][KK - 1]; }
                    v = fmaf(-2.f, ac[3], xn[mg * 2 + 1] + yn1);
                    if (v < thr[mg * 2 + 1]) { top9_shift(tk[mg * 2 + 1], v); thr[mg * 2 + 1] = tk[mg * 2 + 1][KK - 1]; }
                }
            }
#pragma unroll
            for (int i = 0; i < 32; ++i) acc[i] = 0.f;
        }

        if (++c6 == NKC) { c6 = 0; ++mi; }
        if (++b3 == NB) b3 = 0;
    }

    // ---- merge 16 per-thread lists per row (cand overlays B buffers) ----
    __syncthreads();
    const int lst = wn * 4 + (l & 3);   // 0..15
#pragma unroll
    for (int g = 0; g < 4; ++g) {
        int r = wm * 32 + (l >> 2) + g * 8;
#pragma unroll
        for (int j = 0; j < KK; ++j)
            cand[r * CAND_STRIDE + lst * KK + j] = tk[g][j];
    }
    __syncthreads();

    if (tid < BM) {
        float* c = &cand[tid * CAND_STRIDE];
        float* o = out + (size_t)(row0 + tid) * KK;
        const int NC = 16 * KK;   // 144
#pragma unroll 1
        for (int k = 0; k < KK; ++k) {
            float mv = c[k];
            int mi2 = k;
            for (int j = k + 1; j < NC; ++j) {
                float v = c[j];
                if (v < mv) { mv = v; mi2 = j; }
            }
            c[mi2] = c[k];
            c[k] = mv;
            o[k] = sqrtf(fmaxf(mv, 0.f));
        }
    }
}

extern "C" void kernel_launch(void* const* d_in, const int* in_sizes, int n_in,
                              void* d_out, int out_size) {
    const float* emb = (const float*)d_in[0];   // [N, D] fp32
    const float* mem = (const float*)d_in[1];   // [M, D] fp32
    float* out = (float*)d_out;                 // [N, K] fp32

    dim3 cb(32, 8);
    conv_all<<<NN / 8 + MM / 8, cb>>>(emb, mem);

    cudaFuncSetAttribute(fapm_mma, cudaFuncAttributeMaxDynamicSharedMemorySize, SMEM_BYTES);
    fapm_mma<<<NN / BM, 256, SMEM_BYTES>>>(out);
}